// round 4
// baseline (speedup 1.0000x reference)
#include <cuda_runtime.h>
#include <cstdint>

typedef unsigned long long ull;

// B=64, T=1024, TF=512, S=1536, D=512, F=32
#define NROW 65536
#define INV_SCALE 0.04419417382415922f   // 1/sqrt(512)
#define LOG2E 1.4426950408889634f

// ---------------- scratch (static __device__, no allocs) ----------------
__device__ float g_Pm[512 * 64];              // cols 0..31: A[c,f], 32..63: CC[c,f]
__device__ float g_c1[32];
__device__ float g_vb[512];
__device__ float g_qz[(size_t)NROW * 64];     // per row: qk[32] | z[32]  (16 MB)
__device__ float g_h[NROW];
__device__ float g_logits[NROW];
__device__ float g_P[NROW];
__device__ float g_fp[4 * 64 * 512];          // partial final sums (4 t-chunks)

// ---------------- helpers ----------------
#define FMA2(acc, a, b) asm("fma.rn.f32x2 %0, %1, %2, %0;" : "+l"(acc) : "l"(a), "l"(b))

__device__ __forceinline__ ull dup2(float v) {
    ull r; unsigned u = __float_as_uint(v);
    asm("mov.b64 %0, {%1, %1};" : "=l"(r) : "r"(u));
    return r;
}
__device__ __forceinline__ float lo32(ull v) { return __uint_as_float((unsigned)(v & 0xffffffffull)); }
__device__ __forceinline__ float hi32(ull v) { return __uint_as_float((unsigned)(v >> 32)); }
__device__ __forceinline__ float ex2(float x) {
    float r; asm("ex2.approx.ftz.f32 %0, %1;" : "=f"(r) : "f"(x)); return r;
}

// ---------------------------------------------------------------------------
// K0: weight precompute.  grid=512 (c), block=128.
//   Pm[c][f]    = sum_d Wq[c,d]*Wk[f,d]           (f<32)  — A
//   Pm[c][32+f] = sum_d1 Wv[f,d1]*Ws[d1,c]                — CC
//   vb[c] = sum_d1 bv[d1]*Ws[d1,c] + bs[c];  c1[f] = sum_d bq[d]*Wk[f,d]
// ---------------------------------------------------------------------------
__global__ __launch_bounds__(128) void k0(
    const float* __restrict__ Wq, const float* __restrict__ bq,
    const float* __restrict__ Wk, const float* __restrict__ Wv,
    const float* __restrict__ bv, const float* __restrict__ Ws,
    const float* __restrict__ bs)
{
    __shared__ float sWq[512], sWsc[512];
    int c = blockIdx.x;
    for (int i = threadIdx.x; i < 512; i += 128) {
        sWq[i]  = Wq[c * 512 + i];
        sWsc[i] = Ws[i * 512 + c];
    }
    __syncthreads();
    int t = threadIdx.x;
    if (t < 32) {
        const float* wk = Wk + t * 512;
        float acc = 0.f;
        #pragma unroll 8
        for (int d = 0; d < 512; d++) acc = fmaf(sWq[d], wk[d], acc);
        g_Pm[c * 64 + t] = acc;
    } else if (t < 64) {
        const float* wv = Wv + (t - 32) * 512;
        float acc = 0.f;
        #pragma unroll 8
        for (int d = 0; d < 512; d++) acc = fmaf(wv[d], sWsc[d], acc);
        g_Pm[c * 64 + t] = acc;
    } else if (t == 64) {
        float acc = bs[c];
        for (int d = 0; d < 512; d++) acc = fmaf(bv[d], sWsc[d], acc);
        g_vb[c] = acc;
    } else if (t >= 96 && c == 0) {
        const float* wk = Wk + (t - 96) * 512;
        float acc = 0.f;
        for (int d = 0; d < 512; d++) acc = fmaf(bq[d], wk[d], acc);
        g_c1[t - 96] = acc;
    }
}

// ---------------------------------------------------------------------------
// K1: qz = y @ Pm (+c1 on cols<32).  [65536 x 512] @ [512 x 64].
// Tile: 128 rows x 64 cols per block (512 blocks, 256 threads).
// Thread: 8 rows (4 packed row-pairs) x 4 cols -> 16 f32x2 accumulators.
// y staged transposed (yT[cc][r]) so row-pairs load as packed ull;
// Pm staged pre-duplicated (sPmD) so no per-iteration packing.
// ---------------------------------------------------------------------------
__global__ __launch_bounds__(256) void k1(const float* __restrict__ y)
{
    __shared__ __align__(16) float yT[32][132];
    __shared__ __align__(16) ull  sPmD[32][64];
    __shared__ float c1s[32];

    int tid = threadIdx.x;
    int rowbase = blockIdx.x * 128;
    if (tid < 32) c1s[tid] = g_c1[tid];

    int colgrp = tid & 15;     // 16 colgrps x 4 cols
    int rowgrp = tid >> 4;     // 16 rowgrps x 8 rows

    ull acc[4][4];
    #pragma unroll
    for (int p = 0; p < 4; p++)
        #pragma unroll
        for (int j = 0; j < 4; j++) acc[p][j] = 0ull;

    for (int c0 = 0; c0 < 512; c0 += 32) {
        __syncthreads();
        // stage yT (transpose 128x32 tile)
        #pragma unroll
        for (int k = 0; k < 4; k++) {
            int e  = (tid + k * 256) * 4;
            int r  = e >> 5;
            int cc = e & 31;
            float4 v = *(const float4*)(y + (size_t)(rowbase + r) * 512 + c0 + cc);
            yT[cc + 0][r] = v.x; yT[cc + 1][r] = v.y;
            yT[cc + 2][r] = v.z; yT[cc + 3][r] = v.w;
        }
        // stage Pm duplicated
        #pragma unroll
        for (int k = 0; k < 8; k++) {
            int l  = tid + k * 256;
            int cc = l >> 6;
            int col = l & 63;
            sPmD[cc][col] = dup2(g_Pm[(c0 + cc) * 64 + col]);
        }
        __syncthreads();

        #pragma unroll 8
        for (int cc = 0; cc < 32; cc++) {
            longlong2 Y0 = *(const longlong2*)&yT[cc][rowgrp * 8];
            longlong2 Y1 = *(const longlong2*)&yT[cc][rowgrp * 8 + 4];
            longlong2 W0 = *(const longlong2*)&sPmD[cc][colgrp * 4];
            longlong2 W1 = *(const longlong2*)&sPmD[cc][colgrp * 4 + 2];
            ull yp[4] = { (ull)Y0.x, (ull)Y0.y, (ull)Y1.x, (ull)Y1.y };
            ull wd[4] = { (ull)W0.x, (ull)W0.y, (ull)W1.x, (ull)W1.y };
            #pragma unroll
            for (int p = 0; p < 4; p++)
                #pragma unroll
                for (int j = 0; j < 4; j++)
                    FMA2(acc[p][j], yp[p], wd[j]);
        }
    }
    // epilogue
    #pragma unroll
    for (int p = 0; p < 4; p++) {
        int r0 = rowbase + rowgrp * 8 + 2 * p;
        #pragma unroll
        for (int j = 0; j < 4; j++) {
            int col = colgrp * 4 + j;
            float add = (col < 32) ? c1s[col] : 0.0f;
            g_qz[(size_t)r0 * 64 + col]       = lo32(acc[p][j]) + add;
            g_qz[(size_t)(r0 + 1) * 64 + col] = hi32(acc[p][j]) + add;
        }
    }
}

// ---------------------------------------------------------------------------
// K1h: h[row] = y[row] . vb.  One warp per row, 8 rows per block.
// ---------------------------------------------------------------------------
__global__ __launch_bounds__(256) void k1h(const float* __restrict__ y)
{
    __shared__ float4 svb[128];
    int tid = threadIdx.x;
    if (tid < 128) svb[tid] = ((const float4*)g_vb)[tid];
    __syncthreads();
    int wid = tid >> 5, lane = tid & 31;
    int row = blockIdx.x * 8 + wid;
    const float4* yr = (const float4*)(y + (size_t)row * 512);
    float acc = 0.f;
    #pragma unroll
    for (int k = 0; k < 4; k++) {
        float4 a = yr[lane + 32 * k];
        float4 b = svb[lane + 32 * k];
        acc += a.x * b.x + a.y * b.y + a.z * b.z + a.w * b.w;
    }
    #pragma unroll
    for (int o = 16; o; o >>= 1) acc += __shfl_xor_sync(~0u, acc, o);
    if (lane == 0) g_h[row] = acc;
}

// ---------------------------------------------------------------------------
// K2: micro-attention. Per thread = one (b,t): loop s over 1536,
//   sc = qk.w[s], zd = z.w[s]; e = exp(sc/SCALE); den += e; num += e*zd.
// logits = (num/den + h) / SCALE.   grid (8,64), 128 threads.
// weather tile staged in smem, broadcast-read as packed f32x2 pairs.
// ---------------------------------------------------------------------------
__global__ __launch_bounds__(128) void k2(
    const float* __restrict__ wh, const float* __restrict__ wf)
{
    __shared__ __align__(16) ull sW[128][16];
    int tid = threadIdx.x;
    int b = blockIdx.y;
    int t = blockIdx.x * 128 + tid;
    size_t row = (size_t)b * 1024 + t;

    ull qk2[16], z2[16];
    const longlong2* qp = (const longlong2*)(g_qz + row * 64);
    #pragma unroll
    for (int j = 0; j < 8; j++) { longlong2 v = qp[j];     qk2[2*j] = (ull)v.x; qk2[2*j+1] = (ull)v.y; }
    #pragma unroll
    for (int j = 0; j < 8; j++) { longlong2 v = qp[8 + j]; z2[2*j]  = (ull)v.x; z2[2*j+1]  = (ull)v.y; }

    float num = 0.f, den = 0.f;
    const float CE = INV_SCALE * LOG2E;

    for (int s0 = 0; s0 < 1536; s0 += 128) {
        __syncthreads();
        const float4* src = (s0 < 1024)
            ? (const float4*)(wh + ((size_t)b * 1024 + s0) * 32)
            : (const float4*)(wf + ((size_t)b * 512 + (s0 - 1024)) * 32);
        #pragma unroll
        for (int k = 0; k < 8; k++)
            ((float4*)sW)[tid + 128 * k] = src[tid + 128 * k];
        __syncthreads();

        #pragma unroll 2
        for (int s = 0; s < 128; s++) {
            const longlong2* wp = (const longlong2*)&sW[s][0];
            ull a0 = 0, a1 = 0, c0 = 0, c1 = 0;
            #pragma unroll
            for (int j = 0; j < 8; j++) {
                longlong2 W = wp[j];
                FMA2(a0, (ull)W.x, qk2[2*j]);
                FMA2(c0, (ull)W.x, z2[2*j]);
                FMA2(a1, (ull)W.y, qk2[2*j+1]);
                FMA2(c1, (ull)W.y, z2[2*j+1]);
            }
            float sc = (lo32(a0) + hi32(a0)) + (lo32(a1) + hi32(a1));
            float zd = (lo32(c0) + hi32(c0)) + (lo32(c1) + hi32(c1));
            float e = ex2(sc * CE);   // scores are O(0.1): no max-subtraction needed
            den += e;
            num = fmaf(e, zd, num);
        }
    }
    g_logits[row] = (num / den + g_h[row]) * INV_SCALE;
}

// ---------------------------------------------------------------------------
// K3a: P = softmax over t (per batch).  64 blocks x 256 threads, 4 t each.
// ---------------------------------------------------------------------------
__global__ __launch_bounds__(256) void k3a()
{
    __shared__ float red[256];
    int b = blockIdx.x, tid = threadIdx.x;
    float l[4];
    #pragma unroll
    for (int k = 0; k < 4; k++) l[k] = g_logits[b * 1024 + tid + 256 * k];
    float m = fmaxf(fmaxf(l[0], l[1]), fmaxf(l[2], l[3]));
    red[tid] = m; __syncthreads();
    for (int o = 128; o; o >>= 1) { if (tid < o) red[tid] = fmaxf(red[tid], red[tid + o]); __syncthreads(); }
    m = red[0]; __syncthreads();
    float e[4], s = 0.f;
    #pragma unroll
    for (int k = 0; k < 4; k++) { e[k] = ex2((l[k] - m) * LOG2E); s += e[k]; }
    red[tid] = s; __syncthreads();
    for (int o = 128; o; o >>= 1) { if (tid < o) red[tid] += red[tid + o]; __syncthreads(); }
    float inv = 1.0f / red[0];
    #pragma unroll
    for (int k = 0; k < 4; k++) g_P[b * 1024 + tid + 256 * k] = e[k] * inv;
}

// ---------------------------------------------------------------------------
// K3b: partial final sums (deterministic, no atomics).
// grid (4 t-chunks, 64 b), 128 threads (one float4 of D each).
// ---------------------------------------------------------------------------
__global__ __launch_bounds__(128) void k3b(const float* __restrict__ y)
{
    int tc = blockIdx.x, b = blockIdx.y, tid = threadIdx.x;
    const float4* yb = (const float4*)(y + ((size_t)b * 1024 + tc * 256) * 512);
    const float*  Pp = g_P + b * 1024 + tc * 256;
    float4 acc = make_float4(0.f, 0.f, 0.f, 0.f);
    #pragma unroll 4
    for (int t = 0; t < 256; t++) {
        float p = Pp[t];
        float4 v = yb[(size_t)t * 128 + tid];
        acc.x = fmaf(p, v.x, acc.x); acc.y = fmaf(p, v.y, acc.y);
        acc.z = fmaf(p, v.z, acc.z); acc.w = fmaf(p, v.w, acc.w);
    }
    ((float4*)g_fp)[((size_t)tc * 64 + b) * 128 + tid] = acc;
}

// ---------------------------------------------------------------------------
// K4: out = y + final (final = sum of 4 partials, broadcast over t).
// ---------------------------------------------------------------------------
__global__ __launch_bounds__(256) void k4(const float* __restrict__ y, float* __restrict__ out)
{
    size_t idx = (size_t)blockIdx.x * 256 + threadIdx.x;   // float4 index, 8388608 total
    int b  = (int)(idx >> 17);        // 1024*512/4 = 131072 float4 per batch
    int d4 = (int)(idx & 127);
    const float4* fp = (const float4*)g_fp;
    float4 f0 = fp[(0 * 64 + b) * 128 + d4];
    float4 f1 = fp[(1 * 64 + b) * 128 + d4];
    float4 f2 = fp[(2 * 64 + b) * 128 + d4];
    float4 f3 = fp[(3 * 64 + b) * 128 + d4];
    float4 v  = ((const float4*)y)[idx];
    float4 o;
    o.x = v.x + ((f0.x + f1.x) + (f2.x + f3.x));
    o.y = v.y + ((f0.y + f1.y) + (f2.y + f3.y));
    o.z = v.z + ((f0.z + f1.z) + (f2.z + f3.z));
    o.w = v.w + ((f0.w + f1.w) + (f2.w + f3.w));
    ((float4*)out)[idx] = o;
}

// ---------------------------------------------------------------------------
extern "C" void kernel_launch(void* const* d_in, const int* in_sizes, int n_in,
                              void* d_out, int out_size)
{
    const float* y  = (const float*)d_in[0];   // [64,1024,512]
    const float* wh = (const float*)d_in[1];   // [64,1024,32]
    const float* wf = (const float*)d_in[2];   // [64,512,32]
    const float* Wq = (const float*)d_in[3];   // [512,512]
    const float* bq = (const float*)d_in[4];   // [512]
    const float* Wk = (const float*)d_in[5];   // [32,512]
    // d_in[6] = bk: drops out of the algebra entirely
    const float* Wv = (const float*)d_in[7];   // [32,512]
    const float* bv = (const float*)d_in[8];   // [512]
    const float* Ws = (const float*)d_in[9];   // [512,512]
    const float* bs = (const float*)d_in[10];  // [512]
    float* out = (float*)d_out;

    k0 <<<512, 128>>>(Wq, bq, Wk, Wv, bv, Ws, bs);
    k1 <<<512, 256>>>(y);
    k1h<<<8192, 256>>>(y);
    k2 <<<dim3(8, 64), 128>>>(wh, wf);
    k3a<<<64, 256>>>();
    k3b<<<dim3(4, 64), 128>>>(y);
    k4 <<<32768, 256>>>(y, out);
}

// round 7
// speedup vs baseline: 2.7903x; 2.7903x over previous
#include <cuda_runtime.h>
#include <cuda_bf16.h>
#include <cstdint>

typedef unsigned long long ull;

// B=64, T=1024, TF=512, S=1536, D=512, F=32
#define NROW 65536
#define INV_SCALE 0.04419417382415922f   // 1/sqrt(512)
#define LOG2E 1.4426950408889634f
#define CE_F (INV_SCALE * LOG2E)

// ---------------- scratch (static __device__, no allocs) ----------------
__device__ __nv_bfloat16 g_PmTb[64 * 512];           // PmT[n][c]: n<32 = A col, n>=32 = CC col
__device__ float g_c1[32];
__device__ float g_vb[512];
__device__ __nv_bfloat16 g_qzb[(size_t)NROW * 64];   // per row: qk*CE+c1*CE [32] | z [32]
__device__ __nv_bfloat16 g_wbf[(size_t)64 * 1536 * 32];
__device__ float g_h[NROW];
__device__ float g_logits[NROW];
__device__ float g_P[NROW];
__device__ float g_fp[4 * 64 * 512];

// ---------------- helpers ----------------
__device__ __forceinline__ float ex2f(float x) {
    float r; asm("ex2.approx.ftz.f32 %0, %1;" : "=f"(r) : "f"(x)); return r;
}

// m16n8k16 row.col bf16 -> f32 (sm_80+, no arch-specific suffix)
__device__ __forceinline__ void mma16816(float& d0, float& d1, float& d2, float& d3,
                                         uint32_t a0, uint32_t a1, uint32_t a2, uint32_t a3,
                                         uint32_t b0, uint32_t b1) {
    asm volatile("mma.sync.aligned.m16n8k16.row.col.f32.bf16.bf16.f32 "
                 "{%0,%1,%2,%3}, {%4,%5,%6,%7}, {%8,%9}, {%0,%1,%2,%3};"
                 : "+f"(d0), "+f"(d1), "+f"(d2), "+f"(d3)
                 : "r"(a0), "r"(a1), "r"(a2), "r"(a3), "r"(b0), "r"(b1));
}

__device__ __forceinline__ uint32_t packbf(float2 p) {
    __nv_bfloat162 v = __floats2bfloat162_rn(p.x, p.y);  // p.x -> low half (k first)
    return *(uint32_t*)&v;
}

// ---------------------------------------------------------------------------
// K0: weight precompute.  grid=512 (c), block=128.
//   PmTb[n][c]: n<32: A[c][n] = sum_d Wq[c,d]*Wk[n,d]
//               n>=32: CC[c][n-32+..] = sum_d Wv[n-32,d]*Ws[d,c]
//   vb[c] = sum_d bv[d]*Ws[d,c] + bs[c];  c1[f] = sum_d bq[d]*Wk[f,d]
// ---------------------------------------------------------------------------
__global__ __launch_bounds__(128) void k0(
    const float* __restrict__ Wq, const float* __restrict__ bq,
    const float* __restrict__ Wk, const float* __restrict__ Wv,
    const float* __restrict__ bv, const float* __restrict__ Ws,
    const float* __restrict__ bs)
{
    __shared__ float sWq[512], sWsc[512];
    int c = blockIdx.x;
    for (int i = threadIdx.x; i < 512; i += 128) {
        sWq[i]  = Wq[c * 512 + i];
        sWsc[i] = Ws[i * 512 + c];
    }
    __syncthreads();
    int t = threadIdx.x;
    if (t < 32) {
        const float* wk = Wk + t * 512;
        float acc = 0.f;
        #pragma unroll 8
        for (int d = 0; d < 512; d++) acc = fmaf(sWq[d], wk[d], acc);
        g_PmTb[t * 512 + c] = __float2bfloat16(acc);
    } else if (t < 64) {
        const float* wv = Wv + (t - 32) * 512;
        float acc = 0.f;
        #pragma unroll 8
        for (int d = 0; d < 512; d++) acc = fmaf(wv[d], sWsc[d], acc);
        g_PmTb[t * 512 + c] = __float2bfloat16(acc);
    } else if (t == 64) {
        float acc = bs[c];
        for (int d = 0; d < 512; d++) acc = fmaf(bv[d], sWsc[d], acc);
        g_vb[c] = acc;
    } else if (t >= 96 && c == 0) {
        const float* wk = Wk + (t - 96) * 512;
        float acc = 0.f;
        for (int d = 0; d < 512; d++) acc = fmaf(bq[d], wk[d], acc);
        g_c1[t - 96] = acc;
    }
}

// ---------------------------------------------------------------------------
// K1M: qz = y @ PmT^T via bf16 mma.sync; fused h = y . vb.
// CTA: 128 rows, 8 warps (m16 each). k=512 in two smem halves of 256.
// B (PmT) staged bf16 in smem, pitch 528 B -> conflict-free frag loads.
// A fragments converted from global fp32 y on the fly.
// Epilogue: (+c1)*CE on cols<32, store bf16 to g_qzb; h reduced per row.
// ---------------------------------------------------------------------------
__global__ __launch_bounds__(256) void k1m(const float* __restrict__ y)
{
    __shared__ __align__(16) char sB[64 * 528];   // 33792 B
    __shared__ float svb[512];
    __shared__ float sc1[32];

    int tid = threadIdx.x;
    int w = tid >> 5, lane = tid & 31;
    int g = lane >> 2, t = lane & 3;
    int R = blockIdx.x * 128 + w * 16;

    for (int i = tid; i < 512; i += 256) svb[i] = g_vb[i];
    if (tid < 32) sc1[tid] = g_c1[tid];

    float acc[8][4];
    #pragma unroll
    for (int n = 0; n < 8; n++) {
        acc[n][0] = 0.f; acc[n][1] = 0.f; acc[n][2] = 0.f; acc[n][3] = 0.f;
    }
    float ha = 0.f, hb = 0.f;

    const float* rowA = y + (size_t)(R + g) * 512;
    const float* rowB = y + (size_t)(R + g + 8) * 512;

    for (int half = 0; half < 2; half++) {
        __syncthreads();
        // stage PmT half: 64 rows x 256 bf16 (pitch 528 B)
        for (int i = tid; i < 2048; i += 256) {
            int r = i >> 5, seg = i & 31;
            *(uint4*)(sB + r * 528 + seg * 16) =
                *(const uint4*)(g_PmTb + (size_t)r * 512 + half * 256 + seg * 8);
        }
        __syncthreads();

        #pragma unroll 4
        for (int ks = 0; ks < 16; ks++) {
            int kg = half * 256 + ks * 16;
            int c  = kg + 2 * t;
            float2 p0 = *(const float2*)(rowA + c);
            float2 p1 = *(const float2*)(rowB + c);
            float2 p2 = *(const float2*)(rowA + c + 8);
            float2 p3 = *(const float2*)(rowB + c + 8);
            ha += p0.x * svb[c] + p0.y * svb[c + 1] + p2.x * svb[c + 8] + p2.y * svb[c + 9];
            hb += p1.x * svb[c] + p1.y * svb[c + 1] + p3.x * svb[c + 8] + p3.y * svb[c + 9];
            uint32_t a0 = packbf(p0), a1 = packbf(p1), a2 = packbf(p2), a3 = packbf(p3);
            const char* bbase = sB + g * 528 + 4 * t + 32 * ks;
            #pragma unroll
            for (int n = 0; n < 8; n++) {
                uint32_t b0 = *(const uint32_t*)(bbase + n * (8 * 528));
                uint32_t b1 = *(const uint32_t*)(bbase + n * (8 * 528) + 16);
                mma16816(acc[n][0], acc[n][1], acc[n][2], acc[n][3], a0, a1, a2, a3, b0, b1);
            }
        }
    }
    // h quad-reduce (sum over t within same g)
    ha += __shfl_xor_sync(~0u, ha, 1); ha += __shfl_xor_sync(~0u, ha, 2);
    hb += __shfl_xor_sync(~0u, hb, 1); hb += __shfl_xor_sync(~0u, hb, 2);
    if (t == 0) { g_h[R + g] = ha; g_h[R + g + 8] = hb; }

    // store qz bf16 (cols<32 get +c1 then *CE)
    #pragma unroll
    for (int n = 0; n < 8; n++) {
        int col = n * 8 + 2 * t;
        float add0 = (n < 4) ? sc1[col] : 0.f;
        float add1 = (n < 4) ? sc1[col + 1] : 0.f;
        float sc   = (n < 4) ? CE_F : 1.0f;
        float v00 = (acc[n][0] + add0) * sc, v01 = (acc[n][1] + add1) * sc;
        float v10 = (acc[n][2] + add0) * sc, v11 = (acc[n][3] + add1) * sc;
        *(__nv_bfloat162*)(g_qzb + (size_t)(R + g) * 64 + col)     = __floats2bfloat162_rn(v00, v01);
        *(__nv_bfloat162*)(g_qzb + (size_t)(R + g + 8) * 64 + col) = __floats2bfloat162_rn(v10, v11);
    }
}

// ---------------------------------------------------------------------------
// KWC: weather -> bf16 contiguous [b][1536][32] (hist then fore).
// ---------------------------------------------------------------------------
__global__ __launch_bounds__(256) void kwc(const float* __restrict__ wh,
                                           const float* __restrict__ wf)
{
    int ip = blockIdx.x * 256 + threadIdx.x;   // pair index, 1572864 total
    int b = ip / 24576;
    int r = ip - b * 24576;
    float2 v;
    if (r < 16384) v = ((const float2*)(wh + (size_t)b * 32768))[r];
    else           v = ((const float2*)(wf + (size_t)b * 16384))[r - 16384];
    ((__nv_bfloat162*)g_wbf)[(size_t)b * 24576 + r] = __floats2bfloat162_rn(v.x, v.y);
}

// ---------------------------------------------------------------------------
// K2M: micro-attention via bf16 mma.sync.
// CTA: b = blockIdx.y, 128-t tile = blockIdx.x, 8 warps (m16 rows each).
// A frags (qk | z) loaded once from g_qzb. Weather staged in smem, 3 chunks
// of 512 s, pitch 80 B (conflict-free). Per 8-s block: 4 MMAs ->
// scores[16x8] + zd[16x8] in registers; ex2 + den/num accumulation inline.
// ---------------------------------------------------------------------------
__global__ __launch_bounds__(256) void k2m()
{
    __shared__ __align__(16) char sW[512 * 80];   // 40960 B

    int tid = threadIdx.x;
    int w = tid >> 5, lane = tid & 31;
    int g = lane >> 2, t = lane & 3;
    int b = blockIdx.y;
    size_t Rbase = (size_t)b * 1024 + blockIdx.x * 128 + w * 16;

    // A fragments: qk (pre-scaled by CE, +c1*CE) and z; 2 k-steps each
    uint32_t qa[2][4], za[2][4];
    #pragma unroll
    for (int ks = 0; ks < 2; ks++) {
        int c = 16 * ks + 2 * t;
        qa[ks][0] = *(const uint32_t*)(g_qzb + (Rbase + g) * 64 + c);
        qa[ks][1] = *(const uint32_t*)(g_qzb + (Rbase + g + 8) * 64 + c);
        qa[ks][2] = *(const uint32_t*)(g_qzb + (Rbase + g) * 64 + c + 8);
        qa[ks][3] = *(const uint32_t*)(g_qzb + (Rbase + g + 8) * 64 + c + 8);
        za[ks][0] = *(const uint32_t*)(g_qzb + (Rbase + g) * 64 + 32 + c);
        za[ks][1] = *(const uint32_t*)(g_qzb + (Rbase + g + 8) * 64 + 32 + c);
        za[ks][2] = *(const uint32_t*)(g_qzb + (Rbase + g) * 64 + 32 + c + 8);
        za[ks][3] = *(const uint32_t*)(g_qzb + (Rbase + g + 8) * 64 + 32 + c + 8);
    }

    float dena = 0.f, numa = 0.f, denb = 0.f, numb = 0.f;

    for (int chunk = 0; chunk < 3; chunk++) {
        __syncthreads();
        // stage 512 s rows x 32 bf16 (64 B) at pitch 80 B
        const uint4* src = (const uint4*)(g_wbf + ((size_t)b * 1536 + chunk * 512) * 32);
        #pragma unroll
        for (int kk = 0; kk < 8; kk++) {
            int i = tid + kk * 256;
            int r = i >> 2, seg = i & 3;
            *(uint4*)(sW + r * 80 + seg * 16) = src[i];
        }
        __syncthreads();

        #pragma unroll 2
        for (int sb = 0; sb < 64; sb++) {
            const char* base = sW + (sb * 8 + g) * 80 + 4 * t;
            uint32_t b0 = *(const uint32_t*)(base);          // k 2t,2t+1
            uint32_t b1 = *(const uint32_t*)(base + 16);     // k 2t+8,2t+9
            uint32_t b2 = *(const uint32_t*)(base + 32);     // k 16+2t
            uint32_t b3 = *(const uint32_t*)(base + 48);     // k 16+2t+8
            float s0 = 0.f, s1 = 0.f, s2 = 0.f, s3 = 0.f;
            float z0 = 0.f, z1 = 0.f, z2 = 0.f, z3 = 0.f;
            mma16816(s0, s1, s2, s3, qa[0][0], qa[0][1], qa[0][2], qa[0][3], b0, b1);
            mma16816(s0, s1, s2, s3, qa[1][0], qa[1][1], qa[1][2], qa[1][3], b2, b3);
            mma16816(z0, z1, z2, z3, za[0][0], za[0][1], za[0][2], za[0][3], b0, b1);
            mma16816(z0, z1, z2, z3, za[1][0], za[1][1], za[1][2], za[1][3], b2, b3);
            float e0 = ex2f(s0), e1 = ex2f(s1), e2 = ex2f(s2), e3 = ex2f(s3);
            dena += e0 + e1;
            numa = fmaf(e0, z0, fmaf(e1, z1, numa));
            denb += e2 + e3;
            numb = fmaf(e2, z2, fmaf(e3, z3, numb));
        }
    }
    // quad-reduce over t (same g)
    dena += __shfl_xor_sync(~0u, dena, 1); dena += __shfl_xor_sync(~0u, dena, 2);
    numa += __shfl_xor_sync(~0u, numa, 1); numa += __shfl_xor_sync(~0u, numa, 2);
    denb += __shfl_xor_sync(~0u, denb, 1); denb += __shfl_xor_sync(~0u, denb, 2);
    numb += __shfl_xor_sync(~0u, numb, 1); numb += __shfl_xor_sync(~0u, numb, 2);
    if (t == 0) {
        size_t r0 = Rbase + g, r1 = Rbase + g + 8;
        g_logits[r0] = (numa / dena + g_h[r0]) * INV_SCALE;
        g_logits[r1] = (numb / denb + g_h[r1]) * INV_SCALE;
    }
}

// ---------------------------------------------------------------------------
// K3a: P = softmax over t (per batch).
// ---------------------------------------------------------------------------
__global__ __launch_bounds__(256) void k3a()
{
    __shared__ float red[256];
    int b = blockIdx.x, tid = threadIdx.x;
    float l[4];
    #pragma unroll
    for (int k = 0; k < 4; k++) l[k] = g_logits[b * 1024 + tid + 256 * k];
    float m = fmaxf(fmaxf(l[0], l[1]), fmaxf(l[2], l[3]));
    red[tid] = m; __syncthreads();
    for (int o = 128; o; o >>= 1) { if (tid < o) red[tid] = fmaxf(red[tid], red[tid + o]); __syncthreads(); }
    m = red[0]; __syncthreads();
    float e[4], s = 0.f;
    #pragma unroll
    for (int k = 0; k < 4; k++) { e[k] = ex2f((l[k] - m) * LOG2E); s += e[k]; }
    red[tid] = s; __syncthreads();
    for (int o = 128; o; o >>= 1) { if (tid < o) red[tid] += red[tid + o]; __syncthreads(); }
    float inv = 1.0f / red[0];
    #pragma unroll
    for (int k = 0; k < 4; k++) g_P[b * 1024 + tid + 256 * k] = e[k] * inv;
}

// ---------------------------------------------------------------------------
// K3b: partial final sums (deterministic).
// ---------------------------------------------------------------------------
__global__ __launch_bounds__(128) void k3b(const float* __restrict__ y)
{
    int tc = blockIdx.x, b = blockIdx.y, tid = threadIdx.x;
    const float4* yb = (const float4*)(y + ((size_t)b * 1024 + tc * 256) * 512);
    const float*  Pp = g_P + b * 1024 + tc * 256;
    float4 acc = make_float4(0.f, 0.f, 0.f, 0.f);
    #pragma unroll 4
    for (int t = 0; t < 256; t++) {
        float p = Pp[t];
        float4 v = yb[(size_t)t * 128 + tid];
        acc.x = fmaf(p, v.x, acc.x); acc.y = fmaf(p, v.y, acc.y);
        acc.z = fmaf(p, v.z, acc.z); acc.w = fmaf(p, v.w, acc.w);
    }
    ((float4*)g_fp)[((size_t)tc * 64 + b) * 128 + tid] = acc;
}

// ---------------------------------------------------------------------------
// K4: out = y + final.
// ---------------------------------------------------------------------------
__global__ __launch_bounds__(256) void k4(const float* __restrict__ y, float* __restrict__ out)
{
    size_t idx = (size_t)blockIdx.x * 256 + threadIdx.x;
    int b  = (int)(idx >> 17);
    int d4 = (int)(idx & 127);
    const float4* fp = (const float4*)g_fp;
    float4 f0 = fp[(0 * 64 + b) * 128 + d4];
    float4 f1 = fp[(1 * 64 + b) * 128 + d4];
    float4 f2 = fp[(2 * 64 + b) * 128 + d4];
    float4 f3 = fp[(3 * 64 + b) * 128 + d4];
    float4 v  = ((const float4*)y)[idx];
    float4 o;
    o.x = v.x + ((f0.x + f1.x) + (f2.x + f3.x));
    o.y = v.y + ((f0.y + f1.y) + (f2.y + f3.y));
    o.z = v.z + ((f0.z + f1.z) + (f2.z + f3.z));
    o.w = v.w + ((f0.w + f1.w) + (f2.w + f3.w));
    ((float4*)out)[idx] = o;
}

// ---------------------------------------------------------------------------
extern "C" void kernel_launch(void* const* d_in, const int* in_sizes, int n_in,
                              void* d_out, int out_size)
{
    const float* y  = (const float*)d_in[0];
    const float* wh = (const float*)d_in[1];
    const float* wf = (const float*)d_in[2];
    const float* Wq = (const float*)d_in[3];
    const float* bq = (const float*)d_in[4];
    const float* Wk = (const float*)d_in[5];
    // d_in[6] = bk: cancels in softmax over s
    const float* Wv = (const float*)d_in[7];
    const float* bv = (const float*)d_in[8];
    const float* Ws = (const float*)d_in[9];
    const float* bs = (const float*)d_in[10];
    float* out = (float*)d_out;

    k0 <<<512, 128>>>(Wq, bq, Wk, Wv, bv, Ws, bs);
    kwc<<<6144, 256>>>(wh, wf);
    k1m<<<512, 256>>>(y);
    k2m<<<dim3(8, 64), 256>>>();
    k3a<<<64, 256>>>();
    k3b<<<dim3(4, 64), 128>>>(y);
    k4 <<<32768, 256>>>(y, out);
}